// round 1
// baseline (speedup 1.0000x reference)
#include <cuda_runtime.h>
#include <cstdint>

// ---------------- problem constants ----------------
#define HID   1024
#define H3    3072
#define NHEADS 16
#define S0T   1088
#define S1T   4096
#define STOT  5184
#define BATCH 4

// ---------------- scratch (device globals; no allocations) ----------------
__device__ float g_qkv0[(size_t)BATCH * S0T * H3];   // ~53 MB
__device__ float g_qkv1[(size_t)BATCH * S1T * H3];   // ~201 MB
__device__ float g_ctx [(size_t)BATCH * STOT * HID]; // ~85 MB
__device__ float g_sc1 [(size_t)64 * 4096 * 128];    // ~128 MB (126 offsets padded to 128)

// ============================================================
// SGEMM with bias + segmented-A gather (handles batch gaps in A rows)
// C[r][c] = sum_k A'[r][k] * B[k][c] + bias[c]
// A'[r] row address = A + r*K + (r/seg)*gap
// Requires M%128==0, N%128==0, K%16==0.
// ============================================================
__global__ __launch_bounds__(256) void sgemm_bias(
    const float* __restrict__ A, int seg, long long gap,
    const float* __restrict__ B, const float* __restrict__ bias,
    float* __restrict__ C, int M, int N, int K)
{
    const int BK = 16;
    __shared__ __align__(16) float As[BK][128];
    __shared__ __align__(16) float Bs[BK][128];

    int tid  = threadIdx.x;
    int row0 = blockIdx.y * 128;
    int col0 = blockIdx.x * 128;

    int aRow = tid >> 2;            // 0..63
    int aCol = (tid & 3) << 2;      // 0,4,8,12
    int bRow = tid >> 5;            // 0..7
    int bCol = (tid & 31) << 2;     // 0..124

    const float* aptr[2];
#pragma unroll
    for (int i = 0; i < 2; i++) {
        int r = row0 + aRow + i * 64;
        aptr[i] = A + (long long)r * K + (long long)(r / seg) * gap + aCol;
    }
    const float* bptr[2];
#pragma unroll
    for (int i = 0; i < 2; i++)
        bptr[i] = B + (long long)(bRow + i * 8) * N + col0 + bCol;

    int ty = tid >> 4, tx = tid & 15;
    float acc[8][8];
#pragma unroll
    for (int i = 0; i < 8; i++)
#pragma unroll
        for (int j = 0; j < 8; j++) acc[i][j] = 0.f;

    for (int k0 = 0; k0 < K; k0 += BK) {
#pragma unroll
        for (int i = 0; i < 2; i++) {
            float4 v = *(const float4*)(aptr[i] + k0);
            As[aCol + 0][aRow + i * 64] = v.x;
            As[aCol + 1][aRow + i * 64] = v.y;
            As[aCol + 2][aRow + i * 64] = v.z;
            As[aCol + 3][aRow + i * 64] = v.w;
        }
#pragma unroll
        for (int i = 0; i < 2; i++) {
            float4 v = *(const float4*)(bptr[i] + (long long)k0 * N);
            *(float4*)&Bs[bRow + i * 8][bCol] = v;
        }
        __syncthreads();
#pragma unroll
        for (int kk = 0; kk < BK; kk++) {
            float a[8], b[8];
            float4 a0 = *(float4*)&As[kk][ty * 8];
            float4 a1 = *(float4*)&As[kk][ty * 8 + 4];
            float4 b0 = *(float4*)&Bs[kk][tx * 8];
            float4 b1 = *(float4*)&Bs[kk][tx * 8 + 4];
            a[0]=a0.x; a[1]=a0.y; a[2]=a0.z; a[3]=a0.w;
            a[4]=a1.x; a[5]=a1.y; a[6]=a1.z; a[7]=a1.w;
            b[0]=b0.x; b[1]=b0.y; b[2]=b0.z; b[3]=b0.w;
            b[4]=b1.x; b[5]=b1.y; b[6]=b1.z; b[7]=b1.w;
#pragma unroll
            for (int i = 0; i < 8; i++)
#pragma unroll
                for (int j = 0; j < 8; j++)
                    acc[i][j] += a[i] * b[j];
        }
        __syncthreads();
    }

#pragma unroll
    for (int i = 0; i < 8; i++) {
        int r = row0 + ty * 8 + i;
        float* cp = C + (long long)r * N + col0 + tx * 8;
        const float* bp = bias + col0 + tx * 8;
        float4 o0 = make_float4(acc[i][0] + bp[0], acc[i][1] + bp[1],
                                acc[i][2] + bp[2], acc[i][3] + bp[3]);
        float4 o1 = make_float4(acc[i][4] + bp[4], acc[i][5] + bp[5],
                                acc[i][6] + bp[6], acc[i][7] + bp[7]);
        *(float4*)cp       = o0;
        *(float4*)(cp + 4) = o1;
    }
}

// ============================================================
// Dense causal attention on segment 0 (flash-style, fp32)
// grid (17, 64): blockIdx.x = q-tile (64 rows), blockIdx.y = b*16+n
// block 64 threads: one query row per thread
// ============================================================
__global__ __launch_bounds__(64) void attn0_kernel()
{
    int qt  = blockIdx.x;
    int bh  = blockIdx.y;
    int b   = bh >> 4, n = bh & 15;
    int tid = threadIdx.x;
    int qi  = qt * 64 + tid;

    __shared__ __align__(16) float Ks[32][64];
    __shared__ __align__(16) float Vs[32][64];
    __shared__ float Ss[64][33];

    const float* qrow = g_qkv0 + ((long long)(b * S0T + qi)) * H3 + n * 64;
    float q[64];
#pragma unroll
    for (int d = 0; d < 64; d += 4) {
        float4 t = *(const float4*)(qrow + d);
        q[d] = t.x * 0.125f; q[d+1] = t.y * 0.125f;
        q[d+2] = t.z * 0.125f; q[d+3] = t.w * 0.125f;
    }
    float o[64];
#pragma unroll
    for (int d = 0; d < 64; d++) o[d] = 0.f;
    float m = -1e30f, l = 0.f;

    int ntiles = 2 * qt + 2;
    for (int kt = 0; kt < ntiles; kt++) {
        int kb = kt * 32;
#pragma unroll
        for (int i = 0; i < 8; i++) {
            int r = i * 4 + (tid >> 4);
            int c = (tid & 15) << 2;
            const float* kp = g_qkv0 + ((long long)(b * S0T + kb + r)) * H3 + HID + n * 64 + c;
            float4 kv = *(const float4*)kp;
            float4 vv = *(const float4*)(kp + HID);
            *(float4*)&Ks[r][c] = kv;
            *(float4*)&Vs[r][c] = vv;
        }
        __syncthreads();

        int kmax = qi - kb + 1;
        if (kmax > 32) kmax = 32;
        float tmax = -1e30f;
        for (int k = 0; k < kmax; k++) {
            float s = 0.f;
#pragma unroll
            for (int d = 0; d < 64; d += 4) {
                float4 kv = *(float4*)&Ks[k][d];
                s += q[d] * kv.x + q[d+1] * kv.y + q[d+2] * kv.z + q[d+3] * kv.w;
            }
            Ss[tid][k] = s;
            tmax = fmaxf(tmax, s);
        }
        if (kmax > 0) {
            float mnew = fmaxf(m, tmax);
            float corr = __expf(m - mnew);
            l *= corr;
#pragma unroll
            for (int d = 0; d < 64; d++) o[d] *= corr;
            for (int k = 0; k < kmax; k++) {
                float p = __expf(Ss[tid][k] - mnew);
                l += p;
#pragma unroll
                for (int d = 0; d < 64; d += 4) {
                    float4 vv = *(float4*)&Vs[k][d];
                    o[d]   += p * vv.x; o[d+1] += p * vv.y;
                    o[d+2] += p * vv.z; o[d+3] += p * vv.w;
                }
            }
            m = mnew;
        }
        __syncthreads();
    }

    float inv = 1.f / l;
    float* cp = g_ctx + ((long long)(b * STOT + qi)) * HID + n * 64;
#pragma unroll
    for (int d = 0; d < 64; d += 4)
        *(float4*)(cp + d) = make_float4(o[d]*inv, o[d+1]*inv, o[d+2]*inv, o[d+3]*inv);
}

// ============================================================
// Local attention scores (49 cross + 77 causal = 126 offsets)
// grid (y=64, bh=64), block 256: thread = (offset-group g=tid&3, x=tid>>2)
// OOB offsets produce score 0 (zero padding), participating in softmax.
// ============================================================
__global__ __launch_bounds__(256) void scores1_kernel()
{
    int tid = threadIdx.x;
    int g = tid & 3, x = tid >> 2;
    int y = blockIdx.x, bh = blockIdx.y;
    int b = bh >> 4, n = bh & 15;

    const float* qp = g_qkv1 + ((long long)(b * S1T + y * 64 + x)) * H3 + n * 64;
    float q[64];
#pragma unroll
    for (int d = 0; d < 64; d += 4) {
        float4 t = *(const float4*)(qp + d);
        q[d] = t.x * 0.125f; q[d+1] = t.y * 0.125f;
        q[d+2] = t.z * 0.125f; q[d+3] = t.w * 0.125f;
    }
    float* srow = g_sc1 + ((long long)bh * 4096 + y * 64 + x) * 128;

    for (int i = 0; i < 32; i++) {
        int o = 4 * i + g;
        if (o >= 126) break;
        const float* kp = nullptr;
        if (o < 49) {                       // cross into segment-0 grid (32x32)
            int dy = o / 7 - 3, dx = o - (o / 7) * 7 - 3;
            int cy = (y >> 1) + dy, cx = (x >> 1) + dx;
            if ((unsigned)cy < 32u && (unsigned)cx < 32u)
                kp = g_qkv0 + ((long long)(b * S0T + 64 + cy * 32 + cx)) * H3 + HID + n * 64;
        } else {                            // causal neighborhood (64x64)
            int oc = o - 49;
            int dy = oc / 9 - 8, dx = oc - (oc / 9) * 9 - 4;
            int yy = y + dy, xx = x + dx;
            if ((unsigned)yy < 64u && (unsigned)xx < 64u)
                kp = g_qkv1 + ((long long)(b * S1T + yy * 64 + xx)) * H3 + HID + n * 64;
        }
        float s = 0.f;
        if (kp) {
#pragma unroll
            for (int d = 0; d < 64; d += 4) {
                float4 kv = *(const float4*)(kp + d);
                s += q[d] * kv.x + q[d+1] * kv.y + q[d+2] * kv.z + q[d+3] * kv.w;
            }
        }
        srow[o] = s;
    }
}

// ============================================================
// Softmax over 126 offsets, in place; one warp per pixel row
// ============================================================
__global__ __launch_bounds__(256) void softmax1_kernel()
{
    int warp = threadIdx.x >> 5, lane = threadIdx.x & 31;
    long long row = (long long)blockIdx.x * 8 + warp;
    float* p = g_sc1 + row * 128;
    float v[4]; float m = -1e30f;
#pragma unroll
    for (int i = 0; i < 4; i++) {
        int o = lane + 32 * i;
        v[i] = (o < 126) ? p[o] : -1e30f;
        m = fmaxf(m, v[i]);
    }
#pragma unroll
    for (int s = 16; s > 0; s >>= 1) m = fmaxf(m, __shfl_xor_sync(0xffffffffu, m, s));
    float sum = 0.f;
#pragma unroll
    for (int i = 0; i < 4; i++) {
        int o = lane + 32 * i;
        float e = (o < 126) ? __expf(v[i] - m) : 0.f;
        v[i] = e; sum += e;
    }
#pragma unroll
    for (int s = 16; s > 0; s >>= 1) sum += __shfl_xor_sync(0xffffffffu, sum, s);
    float inv = 1.f / sum;
#pragma unroll
    for (int i = 0; i < 4; i++) {
        int o = lane + 32 * i;
        if (o < 126) p[o] = v[i] * inv;
    }
}

// ============================================================
// Local attention weighting: ctx1 = sum_o p_o * v_o
// grid (y=64, bh=64), block 256: thread = (ch-group dg=tid&3 of 16, x=tid>>2)
// ============================================================
__global__ __launch_bounds__(256) void weight1_kernel()
{
    int tid = threadIdx.x;
    int dg = tid & 3, x = tid >> 2;
    int y = blockIdx.x, bh = blockIdx.y;
    int b = bh >> 4, n = bh & 15;

    const float* prow = g_sc1 + ((long long)bh * 4096 + y * 64 + x) * 128;
    float acc[16];
#pragma unroll
    for (int i = 0; i < 16; i++) acc[i] = 0.f;

    for (int o = 0; o < 126; o++) {
        const float* vp = nullptr;
        if (o < 49) {
            int dy = o / 7 - 3, dx = o - (o / 7) * 7 - 3;
            int cy = (y >> 1) + dy, cx = (x >> 1) + dx;
            if ((unsigned)cy < 32u && (unsigned)cx < 32u)
                vp = g_qkv0 + ((long long)(b * S0T + 64 + cy * 32 + cx)) * H3 + 2 * HID + n * 64 + dg * 16;
        } else {
            int oc = o - 49;
            int dy = oc / 9 - 8, dx = oc - (oc / 9) * 9 - 4;
            int yy = y + dy, xx = x + dx;
            if ((unsigned)yy < 64u && (unsigned)xx < 64u)
                vp = g_qkv1 + ((long long)(b * S1T + yy * 64 + xx)) * H3 + 2 * HID + n * 64 + dg * 16;
        }
        if (vp) {
            float p = prow[o];
#pragma unroll
            for (int i = 0; i < 16; i += 4) {
                float4 v4 = *(const float4*)(vp + i);
                acc[i]   += p * v4.x; acc[i+1] += p * v4.y;
                acc[i+2] += p * v4.z; acc[i+3] += p * v4.w;
            }
        }
    }
    float* cp = g_ctx + ((long long)(b * STOT + S0T + y * 64 + x)) * HID + n * 64 + dg * 16;
#pragma unroll
    for (int i = 0; i < 16; i += 4)
        *(float4*)(cp + i) = make_float4(acc[i], acc[i+1], acc[i+2], acc[i+3]);
}

// ============================================================
// launch
// ============================================================
extern "C" void kernel_launch(void* const* d_in, const int* in_sizes, int n_in,
                              void* d_out, int out_size)
{
    const float* hs      = (const float*)d_in[0];
    // d_in[1] = mask: exactly tril(S0,S0); implemented analytically
    const float* W_qkv   = (const float*)d_in[2];
    const float* b_qkv   = (const float*)d_in[3];
    const float* W_qkvp  = (const float*)d_in[4];
    const float* b_qkvp  = (const float*)d_in[5];
    const float* W_dense = (const float*)d_in[6];
    const float* b_dense = (const float*)d_in[7];
    float* out = (float*)d_out;

    float *qkv0, *qkv1, *ctx;
    cudaGetSymbolAddress((void**)&qkv0, g_qkv0);
    cudaGetSymbolAddress((void**)&qkv1, g_qkv1);
    cudaGetSymbolAddress((void**)&ctx,  g_ctx);

    // QKV projections
    sgemm_bias<<<dim3(24, 34),  256>>>(hs, S0T, (long long)(STOT - S0T) * HID,
                                       W_qkv, b_qkv, qkv0, BATCH * S0T, H3, HID);
    sgemm_bias<<<dim3(24, 128), 256>>>(hs + (long long)S0T * HID, S1T,
                                       (long long)(STOT - S1T) * HID,
                                       W_qkvp, b_qkvp, qkv1, BATCH * S1T, H3, HID);
    // dense causal attention on segment 0
    attn0_kernel<<<dim3(17, 64), 64>>>();
    // local + cross attention on segment 1
    scores1_kernel<<<dim3(64, 64), 256>>>();
    softmax1_kernel<<<32768, 256>>>();
    weight1_kernel<<<dim3(64, 64), 256>>>();
    // output projection
    sgemm_bias<<<dim3(8, 162), 256>>>(ctx, 1 << 30, 0,
                                      W_dense, b_dense, out, BATCH * STOT, HID, HID);
}

// round 3
// speedup vs baseline: 1.5008x; 1.5008x over previous
#include <cuda_runtime.h>
#include <cuda_bf16.h>
#include <cstdint>

// ---------------- problem constants ----------------
#define HID   1024
#define H3    3072
#define S0T   1088
#define S1T   4096
#define STOT  5184
#define BATCH 4

// ---------------- scratch (device globals; no allocations) ----------------
__device__ float g_qkv0[(size_t)BATCH * S0T * H3];   // ~53 MB
__device__ float g_qkv1[(size_t)BATCH * S1T * H3];   // ~201 MB
__device__ float g_ctx [(size_t)BATCH * STOT * HID]; // ~85 MB
__device__ float g_sc1 [(size_t)64 * 4096 * 128];    // ~128 MB

// ---------------- mma helpers ----------------
static __device__ __forceinline__ uint32_t smem_u32(const void* p) {
    return (uint32_t)__cvta_generic_to_shared(p);
}
static __device__ __forceinline__ void ldsm_x4(uint32_t addr, uint32_t* r) {
    asm volatile("ldmatrix.sync.aligned.m8n8.x4.shared.b16 {%0,%1,%2,%3}, [%4];"
                 : "=r"(r[0]), "=r"(r[1]), "=r"(r[2]), "=r"(r[3]) : "r"(addr));
}
static __device__ __forceinline__ void ldsm_x4_t(uint32_t addr, uint32_t* r) {
    asm volatile("ldmatrix.sync.aligned.m8n8.x4.trans.shared.b16 {%0,%1,%2,%3}, [%4];"
                 : "=r"(r[0]), "=r"(r[1]), "=r"(r[2]), "=r"(r[3]) : "r"(addr));
}
static __device__ __forceinline__ void mma_bf16(float* d, const uint32_t* a, uint32_t b0, uint32_t b1) {
    asm volatile("mma.sync.aligned.m16n8k16.row.col.f32.bf16.bf16.f32 "
                 "{%0,%1,%2,%3}, {%4,%5,%6,%7}, {%8,%9}, {%0,%1,%2,%3};"
                 : "+f"(d[0]), "+f"(d[1]), "+f"(d[2]), "+f"(d[3])
                 : "r"(a[0]), "r"(a[1]), "r"(a[2]), "r"(a[3]), "r"(b0), "r"(b1));
}

// ============================================================
// bf16x3 tensor-core GEMM with bias + segmented-A gather
// C[r][c] = sum_k A'[r][k]*B[k][c] + bias[c],  A'[r] = A + r*K + (r/seg)*gap
// Block 128x128, BK=32, 256 threads (8 warps, 64x32 warp tiles).
// Requires M%128==0, N%128==0, K%32==0.
// ============================================================
__global__ __launch_bounds__(256) void gemm_bf16x3(
    const float* __restrict__ A, int seg, long long gap,
    const float* __restrict__ B, const float* __restrict__ bias,
    float* __restrict__ C, int M, int N, int K)
{
    // A tiles: 128 rows x 32 k, row stride padded to 40 bf16 (80B) -> LDSM conflict-free
    __shared__ __align__(16) __nv_bfloat16 Ahi[128 * 40];
    __shared__ __align__(16) __nv_bfloat16 Alo[128 * 40];
    // B tiles: 32 k x 128 n, 16B-chunk XOR swizzle: chunk' = chunk ^ (k&7)
    __shared__ __align__(16) __nv_bfloat16 Bhi[32 * 128];
    __shared__ __align__(16) __nv_bfloat16 Blo[32 * 128];

    const int tid  = threadIdx.x;
    const int lane = tid & 31;
    const int wid  = tid >> 5;
    const int warpM = wid & 1;      // 2 along M
    const int warpN = wid >> 1;     // 4 along N
    const int row0 = blockIdx.y * 128;
    const int col0 = blockIdx.x * 128;

    // global A: thread -> 4 rows (stride 32), fixed 4-col group
    const int aRow = tid >> 3;           // 0..31
    const int aCol = (tid & 7) << 2;     // 0..28
    const float* aptr[4];
#pragma unroll
    for (int i = 0; i < 4; i++) {
        int r = row0 + aRow + 32 * i;
        aptr[i] = A + (long long)r * K + (long long)(r / seg) * gap + aCol;
    }
    // global B: thread -> 4 k-rows (stride 8), fixed 4-col group
    const int bK   = tid >> 5;           // 0..7
    const int bCol = (tid & 31) << 2;    // 0..124
    const float* bptr = B + (long long)bK * N + col0 + bCol;

    const uint32_t ahiB = smem_u32(Ahi), aloB = smem_u32(Alo);
    const uint32_t bhiB = smem_u32(Bhi), bloB = smem_u32(Blo);

    float acc[4][4][4];
#pragma unroll
    for (int mt = 0; mt < 4; mt++)
#pragma unroll
        for (int nt = 0; nt < 4; nt++)
#pragma unroll
            for (int e = 0; e < 4; e++) acc[mt][nt][e] = 0.f;

    // prefetch first tile
    float4 aReg[4], bReg[4];
#pragma unroll
    for (int i = 0; i < 4; i++) aReg[i] = *(const float4*)(aptr[i]);
#pragma unroll
    for (int i = 0; i < 4; i++) bReg[i] = *(const float4*)(bptr + (long long)(8 * i) * N);

    for (int k0 = 0; k0 < K; k0 += 32) {
        // ---- store prefetched tile to smem with bf16 hi/lo split ----
#pragma unroll
        for (int i = 0; i < 4; i++) {
            float4 v = aReg[i];
            __nv_bfloat16 h0 = __float2bfloat16(v.x), h1 = __float2bfloat16(v.y);
            __nv_bfloat16 h2 = __float2bfloat16(v.z), h3 = __float2bfloat16(v.w);
            __nv_bfloat16 l0 = __float2bfloat16(v.x - __bfloat162float(h0));
            __nv_bfloat16 l1 = __float2bfloat16(v.y - __bfloat162float(h1));
            __nv_bfloat16 l2 = __float2bfloat16(v.z - __bfloat162float(h2));
            __nv_bfloat16 l3 = __float2bfloat16(v.w - __bfloat162float(h3));
            int off = (aRow + 32 * i) * 40 + aCol;
            ((__nv_bfloat162*)(Ahi + off))[0] = __nv_bfloat162(h0, h1);
            ((__nv_bfloat162*)(Ahi + off))[1] = __nv_bfloat162(h2, h3);
            ((__nv_bfloat162*)(Alo + off))[0] = __nv_bfloat162(l0, l1);
            ((__nv_bfloat162*)(Alo + off))[1] = __nv_bfloat162(l2, l3);
        }
#pragma unroll
        for (int i = 0; i < 4; i++) {
            float4 v = bReg[i];
            int k = bK + 8 * i;
            __nv_bfloat16 h0 = __float2bfloat16(v.x), h1 = __float2bfloat16(v.y);
            __nv_bfloat16 h2 = __float2bfloat16(v.z), h3 = __float2bfloat16(v.w);
            __nv_bfloat16 l0 = __float2bfloat16(v.x - __bfloat162float(h0));
            __nv_bfloat16 l1 = __float2bfloat16(v.y - __bfloat162float(h1));
            __nv_bfloat16 l2 = __float2bfloat16(v.z - __bfloat162float(h2));
            __nv_bfloat16 l3 = __float2bfloat16(v.w - __bfloat162float(h3));
            int sw  = (bCol >> 3) ^ (k & 7);
            int off = k * 128 + sw * 8 + ((bCol >> 2) & 1) * 4;
            ((__nv_bfloat162*)(Bhi + off))[0] = __nv_bfloat162(h0, h1);
            ((__nv_bfloat162*)(Bhi + off))[1] = __nv_bfloat162(h2, h3);
            ((__nv_bfloat162*)(Blo + off))[0] = __nv_bfloat162(l0, l1);
            ((__nv_bfloat162*)(Blo + off))[1] = __nv_bfloat162(l2, l3);
        }
        __syncthreads();

        // ---- prefetch next tile (overlaps with mma) ----
        if (k0 + 32 < K) {
#pragma unroll
            for (int i = 0; i < 4; i++) aReg[i] = *(const float4*)(aptr[i] + k0 + 32);
#pragma unroll
            for (int i = 0; i < 4; i++)
                bReg[i] = *(const float4*)(bptr + (long long)(k0 + 32 + 8 * i) * N);
        }

        // ---- compute ----
#pragma unroll
        for (int ks = 0; ks < 2; ks++) {
            uint32_t ah[4][4], al[4][4];
#pragma unroll
            for (int mt = 0; mt < 4; mt++) {
                int row = warpM * 64 + mt * 16 + (lane & 15);
                uint32_t boff = row * 80 + ks * 32 + (lane >> 4) * 16;
                ldsm_x4(ahiB + boff, ah[mt]);
                ldsm_x4(aloB + boff, al[mt]);
            }
            uint32_t bh[2][4], bl[2][4];
#pragma unroll
            for (int np = 0; np < 2; np++) {
                int k    = (lane & 15) + ks * 16;
                int ncol = warpN * 32 + np * 16 + (lane >> 4) * 8;
                uint32_t boff = k * 256 + (((ncol >> 3) ^ (k & 7)) << 4);
                ldsm_x4_t(bhiB + boff, bh[np]);
                ldsm_x4_t(bloB + boff, bl[np]);
            }
#pragma unroll
            for (int mt = 0; mt < 4; mt++)
#pragma unroll
                for (int np = 0; np < 2; np++)
#pragma unroll
                    for (int h = 0; h < 2; h++) {
                        float* d = acc[mt][np * 2 + h];
                        mma_bf16(d, ah[mt], bh[np][h * 2], bh[np][h * 2 + 1]); // hi*hi
                        mma_bf16(d, ah[mt], bl[np][h * 2], bl[np][h * 2 + 1]); // hi*lo
                        mma_bf16(d, al[mt], bh[np][h * 2], bh[np][h * 2 + 1]); // lo*hi
                    }
        }
        __syncthreads();
    }

    // ---- epilogue: bias + store ----
#pragma unroll
    for (int mt = 0; mt < 4; mt++) {
        int r = row0 + warpM * 64 + mt * 16 + (lane >> 2);
#pragma unroll
        for (int nt = 0; nt < 4; nt++) {
            int c = col0 + warpN * 32 + nt * 8 + (lane & 3) * 2;
            float b0 = bias[c], b1 = bias[c + 1];
            float2 o0 = make_float2(acc[mt][nt][0] + b0, acc[mt][nt][1] + b1);
            float2 o1 = make_float2(acc[mt][nt][2] + b0, acc[mt][nt][3] + b1);
            *(float2*)(C + (long long)r * N + c)       = o0;
            *(float2*)(C + (long long)(r + 8) * N + c) = o1;
        }
    }
}

// ============================================================
// Dense causal attention on segment 0 (flash-style, fp32)
// ============================================================
__global__ __launch_bounds__(64) void attn0_kernel()
{
    int qt  = blockIdx.x;
    int bh  = blockIdx.y;
    int b   = bh >> 4, n = bh & 15;
    int tid = threadIdx.x;
    int qi  = qt * 64 + tid;

    __shared__ __align__(16) float Ks[32][64];
    __shared__ __align__(16) float Vs[32][64];
    __shared__ float Ss[64][33];

    const float* qrow = g_qkv0 + ((long long)(b * S0T + qi)) * H3 + n * 64;
    float q[64];
#pragma unroll
    for (int d = 0; d < 64; d += 4) {
        float4 t = *(const float4*)(qrow + d);
        q[d] = t.x * 0.125f; q[d+1] = t.y * 0.125f;
        q[d+2] = t.z * 0.125f; q[d+3] = t.w * 0.125f;
    }
    float o[64];
#pragma unroll
    for (int d = 0; d < 64; d++) o[d] = 0.f;
    float m = -1e30f, l = 0.f;

    int ntiles = 2 * qt + 2;
    for (int kt = 0; kt < ntiles; kt++) {
        int kb = kt * 32;
#pragma unroll
        for (int i = 0; i < 8; i++) {
            int r = i * 4 + (tid >> 4);
            int c = (tid & 15) << 2;
            const float* kp = g_qkv0 + ((long long)(b * S0T + kb + r)) * H3 + HID + n * 64 + c;
            float4 kv = *(const float4*)kp;
            float4 vv = *(const float4*)(kp + HID);
            *(float4*)&Ks[r][c] = kv;
            *(float4*)&Vs[r][c] = vv;
        }
        __syncthreads();

        int kmax = qi - kb + 1;
        if (kmax > 32) kmax = 32;
        float tmax = -1e30f;
        for (int k = 0; k < kmax; k++) {
            float s = 0.f;
#pragma unroll
            for (int d = 0; d < 64; d += 4) {
                float4 kv = *(float4*)&Ks[k][d];
                s += q[d] * kv.x + q[d+1] * kv.y + q[d+2] * kv.z + q[d+3] * kv.w;
            }
            Ss[tid][k] = s;
            tmax = fmaxf(tmax, s);
        }
        if (kmax > 0) {
            float mnew = fmaxf(m, tmax);
            float corr = __expf(m - mnew);
            l *= corr;
#pragma unroll
            for (int d = 0; d < 64; d++) o[d] *= corr;
            for (int k = 0; k < kmax; k++) {
                float p = __expf(Ss[tid][k] - mnew);
                l += p;
#pragma unroll
                for (int d = 0; d < 64; d += 4) {
                    float4 vv = *(float4*)&Vs[k][d];
                    o[d]   += p * vv.x; o[d+1] += p * vv.y;
                    o[d+2] += p * vv.z; o[d+3] += p * vv.w;
                }
            }
            m = mnew;
        }
        __syncthreads();
    }

    float inv = 1.f / l;
    float* cp = g_ctx + ((long long)(b * STOT + qi)) * HID + n * 64;
#pragma unroll
    for (int d = 0; d < 64; d += 4)
        *(float4*)(cp + d) = make_float4(o[d]*inv, o[d+1]*inv, o[d+2]*inv, o[d+3]*inv);
}

// ============================================================
// Local attention scores (49 cross + 77 causal = 126 offsets)
// ============================================================
__global__ __launch_bounds__(256) void scores1_kernel()
{
    int tid = threadIdx.x;
    int g = tid & 3, x = tid >> 2;
    int y = blockIdx.x, bh = blockIdx.y;
    int b = bh >> 4, n = bh & 15;

    const float* qp = g_qkv1 + ((long long)(b * S1T + y * 64 + x)) * H3 + n * 64;
    float q[64];
#pragma unroll
    for (int d = 0; d < 64; d += 4) {
        float4 t = *(const float4*)(qp + d);
        q[d] = t.x * 0.125f; q[d+1] = t.y * 0.125f;
        q[d+2] = t.z * 0.125f; q[d+3] = t.w * 0.125f;
    }
    float* srow = g_sc1 + ((long long)bh * 4096 + y * 64 + x) * 128;

    for (int i = 0; i < 32; i++) {
        int o = 4 * i + g;
        if (o >= 126) break;
        const float* kp = nullptr;
        if (o < 49) {
            int dy = o / 7 - 3, dx = o - (o / 7) * 7 - 3;
            int cy = (y >> 1) + dy, cx = (x >> 1) + dx;
            if ((unsigned)cy < 32u && (unsigned)cx < 32u)
                kp = g_qkv0 + ((long long)(b * S0T + 64 + cy * 32 + cx)) * H3 + HID + n * 64;
        } else {
            int oc = o - 49;
            int dy = oc / 9 - 8, dx = oc - (oc / 9) * 9 - 4;
            int yy = y + dy, xx = x + dx;
            if ((unsigned)yy < 64u && (unsigned)xx < 64u)
                kp = g_qkv1 + ((long long)(b * S1T + yy * 64 + xx)) * H3 + HID + n * 64;
        }
        float s = 0.f;
        if (kp) {
#pragma unroll
            for (int d = 0; d < 64; d += 4) {
                float4 kv = *(const float4*)(kp + d);
                s += q[d] * kv.x + q[d+1] * kv.y + q[d+2] * kv.z + q[d+3] * kv.w;
            }
        }
        srow[o] = s;
    }
}

// ============================================================
// Softmax over 126 offsets, in place; one warp per pixel row
// ============================================================
__global__ __launch_bounds__(256) void softmax1_kernel()
{
    int warp = threadIdx.x >> 5, lane = threadIdx.x & 31;
    long long row = (long long)blockIdx.x * 8 + warp;
    float* p = g_sc1 + row * 128;
    float v[4]; float m = -1e30f;
#pragma unroll
    for (int i = 0; i < 4; i++) {
        int o = lane + 32 * i;
        v[i] = (o < 126) ? p[o] : -1e30f;
        m = fmaxf(m, v[i]);
    }
#pragma unroll
    for (int s = 16; s > 0; s >>= 1) m = fmaxf(m, __shfl_xor_sync(0xffffffffu, m, s));
    float sum = 0.f;
#pragma unroll
    for (int i = 0; i < 4; i++) {
        int o = lane + 32 * i;
        float e = (o < 126) ? __expf(v[i] - m) : 0.f;
        v[i] = e; sum += e;
    }
#pragma unroll
    for (int s = 16; s > 0; s >>= 1) sum += __shfl_xor_sync(0xffffffffu, sum, s);
    float inv = 1.f / sum;
#pragma unroll
    for (int i = 0; i < 4; i++) {
        int o = lane + 32 * i;
        if (o < 126) p[o] = v[i] * inv;
    }
}

// ============================================================
// Local attention weighting: ctx1 = sum_o p_o * v_o
// ============================================================
__global__ __launch_bounds__(256) void weight1_kernel()
{
    int tid = threadIdx.x;
    int dg = tid & 3, x = tid >> 2;
    int y = blockIdx.x, bh = blockIdx.y;
    int b = bh >> 4, n = bh & 15;

    const float* prow = g_sc1 + ((long long)bh * 4096 + y * 64 + x) * 128;
    float acc[16];
#pragma unroll
    for (int i = 0; i < 16; i++) acc[i] = 0.f;

    for (int o = 0; o < 126; o++) {
        const float* vp = nullptr;
        if (o < 49) {
            int dy = o / 7 - 3, dx = o - (o / 7) * 7 - 3;
            int cy = (y >> 1) + dy, cx = (x >> 1) + dx;
            if ((unsigned)cy < 32u && (unsigned)cx < 32u)
                vp = g_qkv0 + ((long long)(b * S0T + 64 + cy * 32 + cx)) * H3 + 2 * HID + n * 64 + dg * 16;
        } else {
            int oc = o - 49;
            int dy = oc / 9 - 8, dx = oc - (oc / 9) * 9 - 4;
            int yy = y + dy, xx = x + dx;
            if ((unsigned)yy < 64u && (unsigned)xx < 64u)
                vp = g_qkv1 + ((long long)(b * S1T + yy * 64 + xx)) * H3 + 2 * HID + n * 64 + dg * 16;
        }
        if (vp) {
            float p = prow[o];
#pragma unroll
            for (int i = 0; i < 16; i += 4) {
                float4 v4 = *(const float4*)(vp + i);
                acc[i]   += p * v4.x; acc[i+1] += p * v4.y;
                acc[i+2] += p * v4.z; acc[i+3] += p * v4.w;
            }
        }
    }
    float* cp = g_ctx + ((long long)(b * STOT + S0T + y * 64 + x)) * HID + n * 64 + dg * 16;
#pragma unroll
    for (int i = 0; i < 16; i += 4)
        *(float4*)(cp + i) = make_float4(acc[i], acc[i+1], acc[i+2], acc[i+3]);
}

// ============================================================
// launch
// ============================================================
extern "C" void kernel_launch(void* const* d_in, const int* in_sizes, int n_in,
                              void* d_out, int out_size)
{
    const float* hs      = (const float*)d_in[0];
    // d_in[1] = mask: exactly tril(S0,S0); implemented analytically
    const float* W_qkv   = (const float*)d_in[2];
    const float* b_qkv   = (const float*)d_in[3];
    const float* W_qkvp  = (const float*)d_in[4];
    const float* b_qkvp  = (const float*)d_in[5];
    const float* W_dense = (const float*)d_in[6];
    const float* b_dense = (const float*)d_in[7];
    float* out = (float*)d_out;

    float *qkv0, *qkv1, *ctx;
    cudaGetSymbolAddress((void**)&qkv0, g_qkv0);
    cudaGetSymbolAddress((void**)&qkv1, g_qkv1);
    cudaGetSymbolAddress((void**)&ctx,  g_ctx);

    // QKV projections (tensor cores, bf16x3)
    gemm_bf16x3<<<dim3(24, 34),  256>>>(hs, S0T, (long long)(STOT - S0T) * HID,
                                        W_qkv, b_qkv, qkv0, BATCH * S0T, H3, HID);
    gemm_bf16x3<<<dim3(24, 128), 256>>>(hs + (long long)S0T * HID, S1T,
                                        (long long)(STOT - S1T) * HID,
                                        W_qkvp, b_qkvp, qkv1, BATCH * S1T, H3, HID);
    // dense causal attention on segment 0
    attn0_kernel<<<dim3(17, 64), 64>>>();
    // local + cross attention on segment 1
    scores1_kernel<<<dim3(64, 64), 256>>>();
    softmax1_kernel<<<32768, 256>>>();
    weight1_kernel<<<dim3(64, 64), 256>>>();
    // output projection
    gemm_bf16x3<<<dim3(8, 162), 256>>>(ctx, 1 << 30, 0,
                                       W_dense, b_dense, out, BATCH * STOT, HID, HID);
}

// round 8
// speedup vs baseline: 1.5476x; 1.0312x over previous
#include <cuda_runtime.h>
#include <cuda_bf16.h>
#include <cstdint>

// ---------------- problem constants ----------------
#define HID   1024
#define H3    3072
#define S0T   1088
#define S1T   4096
#define STOT  5184
#define BATCH 4

#define W_ELEMS  ((size_t)HID * H3)             // 3,145,728
#define WD_ELEMS ((size_t)HID * HID)            // 1,048,576

// ---------------- scratch (device globals; no allocations) ----------------
__device__ float g_qkv0[(size_t)BATCH * S0T * H3];   // ~53 MB
__device__ float g_qkv1[(size_t)BATCH * S1T * H3];   // ~201 MB
__device__ float g_ctx [(size_t)BATCH * STOT * HID]; // ~85 MB
__device__ float g_sc1 [(size_t)64 * 4096 * 128];    // ~128 MB

__device__ __nv_bfloat16 g_wq_hi[W_ELEMS],  g_wq_lo[W_ELEMS];
__device__ __nv_bfloat16 g_wp_hi[W_ELEMS],  g_wp_lo[W_ELEMS];
__device__ __nv_bfloat16 g_wd_hi[WD_ELEMS], g_wd_lo[WD_ELEMS];

// ---------------- mma helpers ----------------
static __device__ __forceinline__ uint32_t smem_u32(const void* p) {
    return (uint32_t)__cvta_generic_to_shared(p);
}
static __device__ __forceinline__ void ldsm_x4(uint32_t addr, uint32_t* r) {
    asm volatile("ldmatrix.sync.aligned.m8n8.x4.shared.b16 {%0,%1,%2,%3}, [%4];"
                 : "=r"(r[0]), "=r"(r[1]), "=r"(r[2]), "=r"(r[3]) : "r"(addr));
}
static __device__ __forceinline__ void ldsm_x4_t(uint32_t addr, uint32_t* r) {
    asm volatile("ldmatrix.sync.aligned.m8n8.x4.trans.shared.b16 {%0,%1,%2,%3}, [%4];"
                 : "=r"(r[0]), "=r"(r[1]), "=r"(r[2]), "=r"(r[3]) : "r"(addr));
}
static __device__ __forceinline__ void mma_bf16(float* d, const uint32_t* a, uint32_t b0, uint32_t b1) {
    asm volatile("mma.sync.aligned.m16n8k16.row.col.f32.bf16.bf16.f32 "
                 "{%0,%1,%2,%3}, {%4,%5,%6,%7}, {%8,%9}, {%0,%1,%2,%3};"
                 : "+f"(d[0]), "+f"(d[1]), "+f"(d[2]), "+f"(d[3])
                 : "r"(a[0]), "r"(a[1]), "r"(a[2]), "r"(a[3]), "r"(b0), "r"(b1));
}

// ============================================================
// fp32 -> bf16 hi/lo split (n % 1024 == 0; 4 elems/thread)
// ============================================================
__global__ __launch_bounds__(256) void convert_kernel(
    const float* __restrict__ src, __nv_bfloat16* __restrict__ hi,
    __nv_bfloat16* __restrict__ lo, long long n)
{
    long long i = ((long long)blockIdx.x * 256 + threadIdx.x) * 4;
    if (i >= n) return;
    float4 v = *(const float4*)(src + i);
    __nv_bfloat16 h0 = __float2bfloat16(v.x), h1 = __float2bfloat16(v.y);
    __nv_bfloat16 h2 = __float2bfloat16(v.z), h3 = __float2bfloat16(v.w);
    __nv_bfloat16 l0 = __float2bfloat16(v.x - __bfloat162float(h0));
    __nv_bfloat16 l1 = __float2bfloat16(v.y - __bfloat162float(h1));
    __nv_bfloat16 l2 = __float2bfloat16(v.z - __bfloat162float(h2));
    __nv_bfloat16 l3 = __float2bfloat16(v.w - __bfloat162float(h3));
    ((__nv_bfloat162*)(hi + i))[0] = __nv_bfloat162(h0, h1);
    ((__nv_bfloat162*)(hi + i))[1] = __nv_bfloat162(h2, h3);
    ((__nv_bfloat162*)(lo + i))[0] = __nv_bfloat162(l0, l1);
    ((__nv_bfloat162*)(lo + i))[1] = __nv_bfloat162(l2, l3);
}

// ============================================================
// bf16x3 tensor-core GEMM: A fp32 (in-loop hi/lo split, as R3),
// B pre-split bf16 hi/lo (direct loads, NO in-loop conversion).
// C[r][c] = sum_k A'[r][k]*B[k][c] + bias[c],  A'[r] = A + r*K + (r/seg)*gap
// Block 128x128, BK=32, 256 threads (8 warps, 64x32 warp tiles).
// M%128==0, N%128==0, K%32==0. Static smem = 36864 B (same as R3).
// ============================================================
__global__ __launch_bounds__(256) void gemm_bf16x3(
    const float* __restrict__ A, int seg, long long gap,
    const __nv_bfloat16* __restrict__ Bhi_g, const __nv_bfloat16* __restrict__ Blo_g,
    const float* __restrict__ bias, float* __restrict__ C, int M, int N, int K)
{
    // A tiles: 128 rows x 32 k, row stride padded to 40 bf16 (80B) -> LDSM conflict-free
    __shared__ __align__(16) __nv_bfloat16 Ahi[128 * 40];
    __shared__ __align__(16) __nv_bfloat16 Alo[128 * 40];
    // B tiles: 32 k x 128 n, 16B-chunk XOR swizzle: chunk' = chunk ^ (k&7)
    __shared__ __align__(16) __nv_bfloat16 Bhi[32 * 128];
    __shared__ __align__(16) __nv_bfloat16 Blo[32 * 128];

    const int tid  = threadIdx.x;
    const int lane = tid & 31;
    const int wid  = tid >> 5;
    const int warpM = wid & 1;      // 2 along M
    const int warpN = wid >> 1;     // 4 along N
    const int row0 = blockIdx.y * 128;
    const int col0 = blockIdx.x * 128;

    // global A: thread -> 4 rows (stride 32), fixed 4-col group (identical to R3)
    const int aRow = tid >> 3;           // 0..31
    const int aCol = (tid & 7) << 2;     // 0..28
    const float* aptr[4];
#pragma unroll
    for (int i = 0; i < 4; i++) {
        int r = row0 + aRow + 32 * i;
        aptr[i] = A + (long long)r * K + (long long)(r / seg) * gap + aCol;
    }
    // global B (pre-split bf16): thread -> k-row (tid>>3), 2 16B chunks
    const int kB = tid >> 3;             // 0..31
    const int c0 = (tid & 7) * 2;        // chunk 0..14 (of 16 per row)
    const __nv_bfloat16* bgh = Bhi_g + (long long)kB * N + col0 + c0 * 8;
    const __nv_bfloat16* bgl = Blo_g + (long long)kB * N + col0 + c0 * 8;
    const uint32_t bDst0 = kB * 256 + ((c0       ^ (kB & 7)) << 4);
    const uint32_t bDst1 = kB * 256 + (((c0 + 1) ^ (kB & 7)) << 4);

    const uint32_t ahiB = smem_u32(Ahi), aloB = smem_u32(Alo);
    const uint32_t bhiB = smem_u32(Bhi), bloB = smem_u32(Blo);

    float acc[4][4][4];
#pragma unroll
    for (int mt = 0; mt < 4; mt++)
#pragma unroll
        for (int nt = 0; nt < 4; nt++)
#pragma unroll
            for (int e = 0; e < 4; e++) acc[mt][nt][e] = 0.f;

    // prefetch first tile
    float4 aReg[4];
    uint4 bh0, bh1, bl0, bl1;
#pragma unroll
    for (int i = 0; i < 4; i++) aReg[i] = *(const float4*)(aptr[i]);
    bh0 = *(const uint4*)(bgh);
    bh1 = *(const uint4*)(bgh + 8);
    bl0 = *(const uint4*)(bgl);
    bl1 = *(const uint4*)(bgl + 8);

    for (int k0 = 0; k0 < K; k0 += 32) {
        // ---- store prefetched tile to smem (A: hi/lo split; B: direct) ----
#pragma unroll
        for (int i = 0; i < 4; i++) {
            float4 v = aReg[i];
            __nv_bfloat16 h0 = __float2bfloat16(v.x), h1 = __float2bfloat16(v.y);
            __nv_bfloat16 h2 = __float2bfloat16(v.z), h3 = __float2bfloat16(v.w);
            __nv_bfloat16 l0 = __float2bfloat16(v.x - __bfloat162float(h0));
            __nv_bfloat16 l1 = __float2bfloat16(v.y - __bfloat162float(h1));
            __nv_bfloat16 l2 = __float2bfloat16(v.z - __bfloat162float(h2));
            __nv_bfloat16 l3 = __float2bfloat16(v.w - __bfloat162float(h3));
            int off = (aRow + 32 * i) * 40 + aCol;
            ((__nv_bfloat162*)(Ahi + off))[0] = __nv_bfloat162(h0, h1);
            ((__nv_bfloat162*)(Ahi + off))[1] = __nv_bfloat162(h2, h3);
            ((__nv_bfloat162*)(Alo + off))[0] = __nv_bfloat162(l0, l1);
            ((__nv_bfloat162*)(Alo + off))[1] = __nv_bfloat162(l2, l3);
        }
        *(uint4*)((char*)Bhi + bDst0) = bh0;
        *(uint4*)((char*)Bhi + bDst1) = bh1;
        *(uint4*)((char*)Blo + bDst0) = bl0;
        *(uint4*)((char*)Blo + bDst1) = bl1;
        __syncthreads();

        // ---- prefetch next tile (overlaps with mma) ----
        if (k0 + 32 < K) {
            long long bo = (long long)(k0 + 32) * N;
#pragma unroll
            for (int i = 0; i < 4; i++) aReg[i] = *(const float4*)(aptr[i] + k0 + 32);
            bh0 = *(const uint4*)(bgh + bo);
            bh1 = *(const uint4*)(bgh + bo + 8);
            bl0 = *(const uint4*)(bgl + bo);
            bl1 = *(const uint4*)(bgl + bo + 8);
        }

        // ---- compute (identical to R3) ----
#pragma unroll
        for (int ks = 0; ks < 2; ks++) {
            uint32_t ah[4][4], al[4][4];
#pragma unroll
            for (int mt = 0; mt < 4; mt++) {
                int row = warpM * 64 + mt * 16 + (lane & 15);
                uint32_t boff = row * 80 + ks * 32 + (lane >> 4) * 16;
                ldsm_x4(ahiB + boff, ah[mt]);
                ldsm_x4(aloB + boff, al[mt]);
            }
            uint32_t bh[2][4], bl[2][4];
#pragma unroll
            for (int np = 0; np < 2; np++) {
                int k    = (lane & 15) + ks * 16;
                int ncol = warpN * 32 + np * 16 + (lane >> 4) * 8;
                uint32_t boff = k * 256 + (((ncol >> 3) ^ (k & 7)) << 4);
                ldsm_x4_t(bhiB + boff, bh[np]);
                ldsm_x4_t(bloB + boff, bl[np]);
            }
#pragma unroll
            for (int mt = 0; mt < 4; mt++)
#pragma unroll
                for (int np = 0; np < 2; np++)
#pragma unroll
                    for (int h = 0; h < 2; h++) {
                        float* d = acc[mt][np * 2 + h];
                        mma_bf16(d, ah[mt], bh[np][h * 2], bh[np][h * 2 + 1]); // hi*hi
                        mma_bf16(d, ah[mt], bl[np][h * 2], bl[np][h * 2 + 1]); // hi*lo
                        mma_bf16(d, al[mt], bh[np][h * 2], bh[np][h * 2 + 1]); // lo*hi
                    }
        }
        __syncthreads();
    }

    // ---- epilogue: bias + store (identical to R3) ----
#pragma unroll
    for (int mt = 0; mt < 4; mt++) {
        int r = row0 + warpM * 64 + mt * 16 + (lane >> 2);
#pragma unroll
        for (int nt = 0; nt < 4; nt++) {
            int c = col0 + warpN * 32 + nt * 8 + (lane & 3) * 2;
            float b0 = bias[c], b1 = bias[c + 1];
            float2 o0 = make_float2(acc[mt][nt][0] + b0, acc[mt][nt][1] + b1);
            float2 o1 = make_float2(acc[mt][nt][2] + b0, acc[mt][nt][3] + b1);
            *(float2*)(C + (long long)r * N + c)       = o0;
            *(float2*)(C + (long long)(r + 8) * N + c) = o1;
        }
    }
}

// ============================================================
// Dense causal attention on segment 0 (flash-style, fp32) — R3 verbatim
// ============================================================
__global__ __launch_bounds__(64) void attn0_kernel()
{
    int qt  = blockIdx.x;
    int bh  = blockIdx.y;
    int b   = bh >> 4, n = bh & 15;
    int tid = threadIdx.x;
    int qi  = qt * 64 + tid;

    __shared__ __align__(16) float Ks[32][64];
    __shared__ __align__(16) float Vs[32][64];
    __shared__ float Ss[64][33];

    const float* qrow = g_qkv0 + ((long long)(b * S0T + qi)) * H3 + n * 64;
    float q[64];
#pragma unroll
    for (int d = 0; d < 64; d += 4) {
        float4 t = *(const float4*)(qrow + d);
        q[d] = t.x * 0.125f; q[d+1] = t.y * 0.125f;
        q[d+2] = t.z * 0.125f; q[d+3] = t.w * 0.125f;
    }
    float o[64];
#pragma unroll
    for (int d = 0; d < 64; d++) o[d] = 0.f;
    float m = -1e30f, l = 0.f;

    int ntiles = 2 * qt + 2;
    for (int kt = 0; kt < ntiles; kt++) {
        int kb = kt * 32;
#pragma unroll
        for (int i = 0; i < 8; i++) {
            int r = i * 4 + (tid >> 4);
            int c = (tid & 15) << 2;
            const float* kp = g_qkv0 + ((long long)(b * S0T + kb + r)) * H3 + HID + n * 64 + c;
            float4 kv = *(const float4*)kp;
            float4 vv = *(const float4*)(kp + HID);
            *(float4*)&Ks[r][c] = kv;
            *(float4*)&Vs[r][c] = vv;
        }
        __syncthreads();

        int kmax = qi - kb + 1;
        if (kmax > 32) kmax = 32;
        float tmax = -1e30f;
        for (int k = 0; k < kmax; k++) {
            float s = 0.f;
#pragma unroll
            for (int d = 0; d < 64; d += 4) {
                float4 kv = *(float4*)&Ks[k][d];
                s += q[d] * kv.x + q[d+1] * kv.y + q[d+2] * kv.z + q[d+3] * kv.w;
            }
            Ss[tid][k] = s;
            tmax = fmaxf(tmax, s);
        }
        if (kmax > 0) {
            float mnew = fmaxf(m, tmax);
            float corr = __expf(m - mnew);
            l *= corr;
#pragma unroll
            for (int d = 0; d < 64; d++) o[d] *= corr;
            for (int k = 0; k < kmax; k++) {
                float p = __expf(Ss[tid][k] - mnew);
                l += p;
#pragma unroll
                for (int d = 0; d < 64; d += 4) {
                    float4 vv = *(float4*)&Vs[k][d];
                    o[d]   += p * vv.x; o[d+1] += p * vv.y;
                    o[d+2] += p * vv.z; o[d+3] += p * vv.w;
                }
            }
            m = mnew;
        }
        __syncthreads();
    }

    float inv = 1.f / l;
    float* cp = g_ctx + ((long long)(b * STOT + qi)) * HID + n * 64;
#pragma unroll
    for (int d = 0; d < 64; d += 4)
        *(float4*)(cp + d) = make_float4(o[d]*inv, o[d+1]*inv, o[d+2]*inv, o[d+3]*inv);
}

// ============================================================
// Local attention scores (49 cross + 77 causal = 126 offsets) — R3 verbatim
// ============================================================
__global__ __launch_bounds__(256) void scores1_kernel()
{
    int tid = threadIdx.x;
    int g = tid & 3, x = tid >> 2;
    int y = blockIdx.x, bh = blockIdx.y;
    int b = bh >> 4, n = bh & 15;

    const float* qp = g_qkv1 + ((long long)(b * S1T + y * 64 + x)) * H3 + n * 64;
    float q[64];
#pragma unroll
    for (int d = 0; d < 64; d += 4) {
        float4 t = *(const float4*)(qp + d);
        q[d] = t.x * 0.125f; q[d+1] = t.y * 0.125f;
        q[d+2] = t.z * 0.125f; q[d+3] = t.w * 0.125f;
    }
    float* srow = g_sc1 + ((long long)bh * 4096 + y * 64 + x) * 128;

    for (int i = 0; i < 32; i++) {
        int o = 4 * i + g;
        if (o >= 126) break;
        const float* kp = nullptr;
        if (o < 49) {
            int dy = o / 7 - 3, dx = o - (o / 7) * 7 - 3;
            int cy = (y >> 1) + dy, cx = (x >> 1) + dx;
            if ((unsigned)cy < 32u && (unsigned)cx < 32u)
                kp = g_qkv0 + ((long long)(b * S0T + 64 + cy * 32 + cx)) * H3 + HID + n * 64;
        } else {
            int oc = o - 49;
            int dy = oc / 9 - 8, dx = oc - (oc / 9) * 9 - 4;
            int yy = y + dy, xx = x + dx;
            if ((unsigned)yy < 64u && (unsigned)xx < 64u)
                kp = g_qkv1 + ((long long)(b * S1T + yy * 64 + xx)) * H3 + HID + n * 64;
        }
        float s = 0.f;
        if (kp) {
#pragma unroll
            for (int d = 0; d < 64; d += 4) {
                float4 kv = *(const float4*)(kp + d);
                s += q[d] * kv.x + q[d+1] * kv.y + q[d+2] * kv.z + q[d+3] * kv.w;
            }
        }
        srow[o] = s;
    }
}

// ============================================================
// Softmax over 126 offsets, in place; one warp per pixel row — R3 verbatim
// ============================================================
__global__ __launch_bounds__(256) void softmax1_kernel()
{
    int warp = threadIdx.x >> 5, lane = threadIdx.x & 31;
    long long row = (long long)blockIdx.x * 8 + warp;
    float* p = g_sc1 + row * 128;
    float v[4]; float m = -1e30f;
#pragma unroll
    for (int i = 0; i < 4; i++) {
        int o = lane + 32 * i;
        v[i] = (o < 126) ? p[o] : -1e30f;
        m = fmaxf(m, v[i]);
    }
#pragma unroll
    for (int s = 16; s > 0; s >>= 1) m = fmaxf(m, __shfl_xor_sync(0xffffffffu, m, s));
    float sum = 0.f;
#pragma unroll
    for (int i = 0; i < 4; i++) {
        int o = lane + 32 * i;
        float e = (o < 126) ? __expf(v[i] - m) : 0.f;
        v[i] = e; sum += e;
    }
#pragma unroll
    for (int s = 16; s > 0; s >>= 1) sum += __shfl_xor_sync(0xffffffffu, sum, s);
    float inv = 1.f / sum;
#pragma unroll
    for (int i = 0; i < 4; i++) {
        int o = lane + 32 * i;
        if (o < 126) p[o] = v[i] * inv;
    }
}

// ============================================================
// Local attention weighting: ctx1 = sum_o p_o * v_o — R3 verbatim
// ============================================================
__global__ __launch_bounds__(256) void weight1_kernel()
{
    int tid = threadIdx.x;
    int dg = tid & 3, x = tid >> 2;
    int y = blockIdx.x, bh = blockIdx.y;
    int b = bh >> 4, n = bh & 15;

    const float* prow = g_sc1 + ((long long)bh * 4096 + y * 64 + x) * 128;
    float acc[16];
#pragma unroll
    for (int i = 0; i < 16; i++) acc[i] = 0.f;

    for (int o = 0; o < 126; o++) {
        const float* vp = nullptr;
        if (o < 49) {
            int dy = o / 7 - 3, dx = o - (o / 7) * 7 - 3;
            int cy = (y >> 1) + dy, cx = (x >> 1) + dx;
            if ((unsigned)cy < 32u && (unsigned)cx < 32u)
                vp = g_qkv0 + ((long long)(b * S0T + 64 + cy * 32 + cx)) * H3 + 2 * HID + n * 64 + dg * 16;
        } else {
            int oc = o - 49;
            int dy = oc / 9 - 8, dx = oc - (oc / 9) * 9 - 4;
            int yy = y + dy, xx = x + dx;
            if ((unsigned)yy < 64u && (unsigned)xx < 64u)
                vp = g_qkv1 + ((long long)(b * S1T + yy * 64 + xx)) * H3 + 2 * HID + n * 64 + dg * 16;
        }
        if (vp) {
            float p = prow[o];
#pragma unroll
            for (int i = 0; i < 16; i += 4) {
                float4 v4 = *(const float4*)(vp + i);
                acc[i]   += p * v4.x; acc[i+1] += p * v4.y;
                acc[i+2] += p * v4.z; acc[i+3] += p * v4.w;
            }
        }
    }
    float* cp = g_ctx + ((long long)(b * STOT + S0T + y * 64 + x)) * HID + n * 64 + dg * 16;
#pragma unroll
    for (int i = 0; i < 16; i += 4)
        *(float4*)(cp + i) = make_float4(acc[i], acc[i+1], acc[i+2], acc[i+3]);
}

// ============================================================
// launch
// ============================================================
extern "C" void kernel_launch(void* const* d_in, const int* in_sizes, int n_in,
                              void* d_out, int out_size)
{
    const float* hs      = (const float*)d_in[0];
    // d_in[1] = mask: exactly tril(S0,S0); implemented analytically
    const float* W_qkv   = (const float*)d_in[2];
    const float* b_qkv   = (const float*)d_in[3];
    const float* W_qkvp  = (const float*)d_in[4];
    const float* b_qkvp  = (const float*)d_in[5];
    const float* W_dense = (const float*)d_in[6];
    const float* b_dense = (const float*)d_in[7];
    float* out = (float*)d_out;

    float *qkv0, *qkv1, *ctx;
    cudaGetSymbolAddress((void**)&qkv0, g_qkv0);
    cudaGetSymbolAddress((void**)&qkv1, g_qkv1);
    cudaGetSymbolAddress((void**)&ctx,  g_ctx);
    __nv_bfloat16 *wq_hi, *wq_lo, *wp_hi, *wp_lo, *wd_hi, *wd_lo;
    cudaGetSymbolAddress((void**)&wq_hi, g_wq_hi); cudaGetSymbolAddress((void**)&wq_lo, g_wq_lo);
    cudaGetSymbolAddress((void**)&wp_hi, g_wp_hi); cudaGetSymbolAddress((void**)&wp_lo, g_wp_lo);
    cudaGetSymbolAddress((void**)&wd_hi, g_wd_hi); cudaGetSymbolAddress((void**)&wd_lo, g_wd_lo);

    // pre-split weights to bf16 hi/lo (one-time, ~30 MB of traffic)
    convert_kernel<<<(int)(W_ELEMS / 1024), 256>>>(W_qkv,  wq_hi, wq_lo, (long long)W_ELEMS);
    convert_kernel<<<(int)(W_ELEMS / 1024), 256>>>(W_qkvp, wp_hi, wp_lo, (long long)W_ELEMS);
    convert_kernel<<<(int)(WD_ELEMS / 1024), 256>>>(W_dense, wd_hi, wd_lo, (long long)WD_ELEMS);

    // QKV projections (tensor cores, bf16x3; B pre-split)
    gemm_bf16x3<<<dim3(24, 34),  256>>>(hs, S0T, (long long)(STOT - S0T) * HID,
                                        wq_hi, wq_lo, b_qkv, qkv0, BATCH * S0T, H3, HID);
    gemm_bf16x3<<<dim3(24, 128), 256>>>(hs + (long long)S0T * HID, S1T,
                                        (long long)(STOT - S1T) * HID,
                                        wp_hi, wp_lo, b_qkvp, qkv1, BATCH * S1T, H3, HID);
    // dense causal attention on segment 0
    attn0_kernel<<<dim3(17, 64), 64>>>();
    // local + cross attention on segment 1
    scores1_kernel<<<dim3(64, 64), 256>>>();
    softmax1_kernel<<<32768, 256>>>();
    weight1_kernel<<<dim3(64, 64), 256>>>();
    // output projection
    gemm_bf16x3<<<dim3(8, 162), 256>>>(ctx, 1 << 30, 0,
                                       wd_hi, wd_lo, b_dense, out, BATCH * STOT, HID, HID);
}